// round 15
// baseline (speedup 1.0000x reference)
#include <cuda_runtime.h>
#include <cuda_fp16.h>
#include <cstdint>

#define DD    512
#define NROWS 32768
#define KCODE 8192
#define TAU1  0.02f
#define TAU2  1.0e-3f
#define L2CAP 32768

// ---------------- device scratch ----------------
__device__ __align__(1024) __half g_xh[NROWS * DD];
__device__ __align__(1024) __half g_ch[KCODE * DD];
__device__ __align__(1024) __half g_cl[KCODE * DD];
__device__ float              g_cn[KCODE];
__device__ int                g_ids[NROWS];
__device__ float              g_c1v[4 * NROWS], g_c2v[4 * NROWS];
__device__ int                g_c1i[4 * NROWS];
__device__ float              g_l2v1[4 * L2CAP], g_l2v2[4 * L2CAP];
__device__ int                g_l2i[4 * L2CAP];
__device__ int                g_counters[2];
__device__ int                g_flaglist[NROWS], g_flaglist2[NROWS];
__device__ unsigned long long g_fix[NROWS];

// ---------------- helpers ----------------
__device__ __forceinline__ uint32_t smem_u32(const void* p) {
    uint32_t a;
    asm("{ .reg .u64 t; cvta.to.shared.u64 t, %1; cvt.u32.u64 %0, t; }" : "=r"(a) : "l"(p));
    return a;
}
__device__ __forceinline__ uint32_t h2u(__half2 h) {
    return *reinterpret_cast<uint32_t*>(&h);
}
__device__ __forceinline__ void ldsm4(uint32_t* r, uint32_t addr) {
    asm volatile("ldmatrix.sync.aligned.m8n8.x4.shared.b16 {%0,%1,%2,%3}, [%4];"
                 : "=r"(r[0]), "=r"(r[1]), "=r"(r[2]), "=r"(r[3]) : "r"(addr));
}
__device__ __forceinline__ void mma16816(float* c, const uint32_t* a, const uint32_t* b) {
    asm volatile("mma.sync.aligned.m16n8k16.row.col.f32.f16.f16.f32 "
                 "{%0,%1,%2,%3}, {%4,%5,%6,%7}, {%8,%9}, {%0,%1,%2,%3};"
                 : "+f"(c[0]), "+f"(c[1]), "+f"(c[2]), "+f"(c[3])
                 : "r"(a[0]), "r"(a[1]), "r"(a[2]), "r"(a[3]), "r"(b[0]), "r"(b[1]));
}
__device__ __forceinline__ void cp16(uint32_t dst, const void* src) {
    asm volatile("cp.async.cg.shared.global [%0], [%1], 16;" :: "r"(dst), "l"(src));
}
__device__ __forceinline__ void cp_commit() { asm volatile("cp.async.commit_group;" ::: "memory"); }
__device__ __forceinline__ void cp_wait1()  { asm volatile("cp.async.wait_group 1;" ::: "memory"); }
__device__ __forceinline__ void cp_wait2()  { asm volatile("cp.async.wait_group 2;" ::: "memory"); }
__device__ __forceinline__ void cp_wait0()  { asm volatile("cp.async.wait_group 0;" ::: "memory"); }
__device__ __forceinline__ void bar_grp64(int id) {
    asm volatile("bar.sync %0, 64;" :: "r"(id) : "memory");
}
__device__ __forceinline__ void sts128(uint32_t addr, uint32_t r0, uint32_t r1, uint32_t r2, uint32_t r3) {
    asm volatile("st.shared.v4.b32 [%0], {%1,%2,%3,%4};" :: "r"(addr), "r"(r0), "r"(r1), "r"(r2), "r"(r3) : "memory");
}

#define BUPD(m, idx, B1, B2, I1) \
    if ((m) < (B2)) { if ((m) < (B1)) { (B2) = (B1); (B1) = (m); (I1) = (idx); } else (B2) = (m); }

#define BMERGE(v, v2, ii, b1, b2, i1) \
    if ((v) < (b1))       { (b2) = fminf((b1), (v2)); (b1) = (v); (i1) = (ii); } \
    else if ((v) == (b1)) { if ((ii) < (i1)) (i1) = (ii); (b2) = fminf((b2), fminf((v), (v2))); } \
    else                  { (b2) = fminf((b2), (v)); }

#define S_B0      131072
#define BSTAGE    32768
#define SMEM_L1   229376
#define L2_XL     65536
#define L2_B0     131072
#define L2_BSTAGE 32768
#define SMEM_L2   196608

// ---------------- kernel 0a: x -> fp16 hi only ----------------
__global__ void split_x_kernel(const float* __restrict__ src,
                               __half* __restrict__ hi, int n4)
{
    int i = blockIdx.x * blockDim.x + threadIdx.x;
    if (i >= n4) return;
    float4 v = ((const float4*)src)[i];
    ((__half2*)hi)[i * 2 + 0] = __half2(__float2half_rn(v.x), __float2half_rn(v.y));
    ((__half2*)hi)[i * 2 + 1] = __half2(__float2half_rn(v.z), __float2half_rn(v.w));
}

// ---------------- kernel 0b: codebook -> fp16 hi/lo + norms (fused) ----------------
__global__ void split_c_kernel(const float* __restrict__ cb,
                               __half* __restrict__ hi, __half* __restrict__ lo)
{
    const int w = (blockIdx.x * blockDim.x + threadIdx.x) >> 5;
    const int lane = threadIdx.x & 31;
    const float4* p = (const float4*)(cb + (size_t)w * DD);
    __half2* ph = (__half2*)(hi + (size_t)w * DD);
    __half2* pl = (__half2*)(lo + (size_t)w * DD);
    float s = 0.f;
#pragma unroll
    for (int i = 0; i < 4; i++) {
        const int e4 = lane + 32 * i;
        float4 v = p[e4];
        s += v.x * v.x + v.y * v.y + v.z * v.z + v.w * v.w;
        __half h0 = __float2half_rn(v.x), h1 = __float2half_rn(v.y);
        __half h2 = __float2half_rn(v.z), h3 = __float2half_rn(v.w);
        ph[e4 * 2 + 0] = __half2(h0, h1);
        ph[e4 * 2 + 1] = __half2(h2, h3);
        pl[e4 * 2 + 0] = __half2(__float2half_rn(v.x - __half2float(h0)),
                                 __float2half_rn(v.y - __half2float(h1)));
        pl[e4 * 2 + 1] = __half2(__float2half_rn(v.z - __half2float(h2)),
                                 __float2half_rn(v.w - __half2float(h3)));
    }
#pragma unroll
    for (int o = 16; o; o >>= 1) s += __shfl_xor_sync(0xffffffffu, s, o);
    if (lane == 0) g_cn[w] = s;
}

// ---------------- kernel 2: level-1 2-pass HMMA, FOUR independent warp-pairs ----------------
__global__ void __launch_bounds__(256, 1)
vq_main()
{
    extern __shared__ char smem[];
    const uint32_t sb = smem_u32(smem);

    const int tid   = threadIdx.x;
    const int lane  = tid & 31;
    const int warp  = tid >> 5;
    const int g     = warp >> 1;
    const int whalf = warp & 1;
    const int gtid  = tid & 63;
    const int g32   = g * 32;
    const int row0  = blockIdx.x * 128;
    const int split = blockIdx.y;
    const int code_base = split * 2048;

    const int arow = whalf * 64 + (lane & 15);
    const int ak   = lane >> 4;
    const int arw  = arow & 7;
    const int nrow = g32 + ((lane >> 4) << 3) + (lane & 7);
    const int bk   = (lane >> 3) & 1;
    const int nrw  = nrow & 7;

    float acc[4][4][4];
    float bb[8], bb2[8];
    int   bi[8];
    float2 nrm[4];
#pragma unroll
    for (int k = 0; k < 8; k++) { bb[k] = 3.0e38f; bb2[k] = 3.0e38f; bi[k] = 0; }

    auto issueB = [&](int t, int stg) {
        const int c = t >> 3, ks = t & 7;
        const uint32_t st = sb + S_B0 + stg * BSTAGE;
        const size_t base = (size_t)(code_base + c * 128) * DD + (size_t)ks * 64;
#pragma unroll
        for (int i = 0; i < 4; i++) {
            const int idx = gtid + i * 64;
            const int r = g32 + (idx >> 3), sg = idx & 7;
            const uint32_t off = r * 128 + ((sg ^ (r & 7)) << 4);
            const size_t bo = base + (size_t)r * DD + sg * 8;
            cp16(st + off,         g_ch + bo);
            cp16(st + 16384 + off, g_cl + bo);
        }
        cp_commit();
    };

    {
#pragma unroll
        for (int i = 0; i < 32; i++) {
            const int idx = tid + i * 256;
            const int r = idx >> 6, gg = idx & 63;
            const int s = gg >> 3, sg = gg & 7;
            const uint32_t dst = sb + s * 16384 + r * 128 + ((sg ^ (r & 7)) << 4);
            cp16(dst, g_xh + (size_t)(row0 + r) * DD + gg * 8);
        }
        cp_commit();
        issueB(0, 0);
        issueB(1, 1);
        cp_wait2();
        __syncthreads();
    }

    auto loadf = [&](uint32_t* ahb, uint32_t* bhb, uint32_t* blb, int kq,
                     uint32_t aA, uint32_t aBh, uint32_t aBl) {
        const int ksg = kq * 2;
#pragma unroll
        for (int mt = 0; mt < 4; mt++) {
            const uint32_t offA = (arow + mt * 16) * 128 + (((ksg + ak) ^ arw) << 4);
            ldsm4(ahb + 4 * mt, aA + offA);
        }
#pragma unroll
        for (int p = 0; p < 2; p++) {
            const uint32_t offB = (nrow + p * 16) * 128 + (((ksg + bk) ^ nrw) << 4);
            ldsm4(bhb + 4 * p, aBh + offB);
            ldsm4(blb + 4 * p, aBl + offB);
        }
    };

    const int barid = 1 + g;
    int scur = 0, snxt2 = 2;
#pragma unroll 1
    for (int t = 0; t < 128; t++) {
        cp_wait1();
        bar_grp64(barid);
        if (t + 2 < 128) issueB(t + 2, snxt2);

        if ((t & 7) == 0) {
            const int c = t >> 3;
            const int ccl0 = code_base + (c << 7) + g32 + ((lane & 3) << 1);
#pragma unroll
            for (int nt = 0; nt < 4; nt++)
                nrm[nt] = __ldg((const float2*)(g_cn + ccl0 + nt * 8));
#pragma unroll
            for (int mt = 0; mt < 4; mt++)
#pragma unroll
                for (int nt = 0; nt < 4; nt++)
#pragma unroll
                    for (int q = 0; q < 4; q++) acc[mt][nt][q] = 0.f;
        }

        {
            const int ks = t & 7;
            const uint32_t aA  = sb + ks * 16384;
            const uint32_t st  = sb + S_B0 + scur * BSTAGE;
            const uint32_t aBh = st, aBl = st + 16384;

            uint32_t ah[2][16], bh[2][8], bl[2][8];
            loadf(ah[0], bh[0], bl[0], 0, aA, aBh, aBl);
#pragma unroll
            for (int kq = 0; kq < 4; kq++) {
                const int cur = kq & 1;
                if (kq < 3) loadf(ah[cur ^ 1], bh[cur ^ 1], bl[cur ^ 1], kq + 1, aA, aBh, aBl);
#pragma unroll
                for (int mt = 0; mt < 4; mt++)
#pragma unroll
                    for (int nt = 0; nt < 4; nt++) {
                        mma16816(acc[mt][nt], ah[cur] + 4 * mt, bh[cur] + 2 * nt);
                        mma16816(acc[mt][nt], ah[cur] + 4 * mt, bl[cur] + 2 * nt);
                    }
            }
        }

        if ((t & 7) == 7) {
            const int c   = t >> 3;
            const int cb0 = code_base + (c << 7) + g32 + ((lane & 3) << 1);
#pragma unroll
            for (int mt = 0; mt < 4; mt++)
#pragma unroll
                for (int nt = 0; nt < 4; nt++) {
                    const int cc = cb0 + nt * 8;
                    const float n0 = nrm[nt].x, n1 = nrm[nt].y;
                    const int k0 = mt * 2, k1 = mt * 2 + 1;
                    float m;
                    m = fmaf(-2.f, acc[mt][nt][0], n0); BUPD(m, cc,     bb[k0], bb2[k0], bi[k0]);
                    m = fmaf(-2.f, acc[mt][nt][1], n1); BUPD(m, cc + 1, bb[k0], bb2[k0], bi[k0]);
                    m = fmaf(-2.f, acc[mt][nt][2], n0); BUPD(m, cc,     bb[k1], bb2[k1], bi[k1]);
                    m = fmaf(-2.f, acc[mt][nt][3], n1); BUPD(m, cc + 1, bb[k1], bb2[k1], bi[k1]);
                }
        }

        scur  = (scur  == 2) ? 0 : scur + 1;
        snxt2 = (snxt2 == 2) ? 0 : snxt2 + 1;
    }

    __syncthreads();
    float* rv  = (float*)(smem);
    float* rv2 = rv + 2048;
    int*   ri  = (int*)(rv2 + 2048);
    const int slot = g * 4 + (lane & 3);
#pragma unroll
    for (int mt = 0; mt < 4; mt++)
#pragma unroll
        for (int h = 0; h < 2; h++) {
            const int k  = mt * 2 + h;
            const int lr = whalf * 64 + mt * 16 + (lane >> 2) + h * 8;
            rv [lr * 16 + slot] = bb[k];
            rv2[lr * 16 + slot] = bb2[k];
            ri [lr * 16 + slot] = bi[k];
        }
    __syncthreads();
    if (tid < 128) {
        float b1 = rv[tid * 16], b2 = rv2[tid * 16];
        int   i1 = ri[tid * 16];
#pragma unroll
        for (int s = 1; s < 16; s++) {
            const float v = rv[tid * 16 + s], v2 = rv2[tid * 16 + s];
            const int   ii = ri[tid * 16 + s];
            BMERGE(v, v2, ii, b1, b2, i1);
        }
        const int o = split * NROWS + row0 + tid;
        g_c1v[o] = b1; g_c2v[o] = b2; g_c1i[o] = i1;
    }
}

// ---------------- kernel 3: merge level-1 splits ----------------
__global__ void merge1_kernel()
{
    const int row = blockIdx.x * blockDim.x + threadIdx.x;
    if (row >= NROWS) return;
    float b1 = 3.0e38f, b2 = 3.0e38f;
    int   i1 = 0;
#pragma unroll
    for (int s = 0; s < 4; s++) {
        const float v  = g_c1v[s * NROWS + row];
        const float v2 = g_c2v[s * NROWS + row];
        const int   ii = g_c1i[s * NROWS + row];
        BMERGE(v, v2, ii, b1, b2, i1);
    }
    g_ids[row] = i1;
    if (b2 - b1 < TAU1) {
        int p = atomicAdd(&g_counters[0], 1);
        if (p < L2CAP) g_flaglist[p] = row;
    }
}

// ---------------- kernel 4: level-2 3-pass HMMA (persistent, grid 64x4, fp32-x gather) ----------------
__global__ void __launch_bounds__(256, 1)
vq_l2(const float* __restrict__ x)
{
    const int active = min(g_counters[0], L2CAP);
    extern __shared__ char smem[];
    const uint32_t sb = smem_u32(smem);

    const int tid  = threadIdx.x;
    const int lane = tid & 31;
    const int warp = tid >> 5;
    const int wm   = warp >> 2;
    const int wn   = warp & 3;
    const int seg  = blockIdx.y;              // 0..3
    const int code0 = seg * 2048;

    const int arow = wm * 32 + (lane & 15);
    const int ak   = lane >> 4;
    const int arw  = arow & 7;
    const int nrow = wn * 32 + ((lane >> 4) << 3) + (lane & 7);
    const int bk   = (lane >> 3) & 1;
    const int nrw  = nrow & 7;

    auto issueB = [&](int t) {
        const int c = t >> 3, ks = t & 7;
        const uint32_t st = sb + L2_B0 + (t & 1) * L2_BSTAGE;
        const size_t base = (size_t)(code0 + c * 128) * DD + (size_t)ks * 64;
#pragma unroll
        for (int i = 0; i < 4; i++) {
            const int idx = tid + i * 256;
            const int r = idx >> 3, sg = idx & 7;
            const uint32_t off = r * 128 + ((sg ^ (r & 7)) << 4);
            const size_t bo = base + (size_t)r * DD + sg * 8;
            cp16(st + off,         g_ch + bo);
            cp16(st + 16384 + off, g_cl + bo);
        }
        cp_commit();
    };

#pragma unroll 1
    for (int slot0 = blockIdx.x * 64; slot0 < active; slot0 += gridDim.x * 64) {
        float acc[2][4][4];
        float bb[4], bb2[4];
        int   bi[4];
#pragma unroll
        for (int k = 0; k < 4; k++) { bb[k] = 3.0e38f; bb2[k] = 3.0e38f; bi[k] = 0; }

        // prologue: gather flagged x rows (fp32) -> hi/lo smem; B stage 0 via cp.async
        {
#pragma unroll
            for (int i = 0; i < 16; i++) {
                const int idx = tid + i * 256;        // 4096 16B-chunks
                const int r = idx >> 6, gg = idx & 63;
                const int s = gg >> 3, sg = gg & 7;
                const int sl = slot0 + r;
                const int grow = __ldg(&g_flaglist[sl < active ? sl : slot0]);
                const float4* xp = (const float4*)(x + (size_t)grow * DD + gg * 8);
                const float4 v0 = __ldg(xp), v1 = __ldg(xp + 1);
                __half h0 = __float2half_rn(v0.x), h1 = __float2half_rn(v0.y);
                __half h2 = __float2half_rn(v0.z), h3 = __float2half_rn(v0.w);
                __half h4 = __float2half_rn(v1.x), h5 = __float2half_rn(v1.y);
                __half h6 = __float2half_rn(v1.z), h7 = __float2half_rn(v1.w);
                __half2 ph0(h0, h1), ph1(h2, h3), ph2(h4, h5), ph3(h6, h7);
                __half2 pl0(__float2half_rn(v0.x - __half2float(h0)), __float2half_rn(v0.y - __half2float(h1)));
                __half2 pl1(__float2half_rn(v0.z - __half2float(h2)), __float2half_rn(v0.w - __half2float(h3)));
                __half2 pl2(__float2half_rn(v1.x - __half2float(h4)), __float2half_rn(v1.y - __half2float(h5)));
                __half2 pl3(__float2half_rn(v1.z - __half2float(h6)), __float2half_rn(v1.w - __half2float(h7)));
                const uint32_t dst = s * 8192 + r * 128 + ((sg ^ (r & 7)) << 4);
                sts128(sb + dst,         h2u(ph0), h2u(ph1), h2u(ph2), h2u(ph3));
                sts128(sb + L2_XL + dst, h2u(pl0), h2u(pl1), h2u(pl2), h2u(pl3));
            }
            const uint32_t st = sb + L2_B0;
            const size_t base = (size_t)code0 * DD;
#pragma unroll
            for (int i = 0; i < 4; i++) {
                const int idx = tid + i * 256;
                const int r = idx >> 3, sg = idx & 7;
                const uint32_t off = r * 128 + ((sg ^ (r & 7)) << 4);
                const size_t bo = base + (size_t)r * DD + sg * 8;
                cp16(st + off,         g_ch + bo);
                cp16(st + 16384 + off, g_cl + bo);
            }
            cp_commit();
        }

#pragma unroll 1
        for (int t = 0; t < 128; t++) {
            if (t + 1 < 128) { issueB(t + 1); cp_wait1(); }
            else             { cp_wait0(); }
            __syncthreads();

            if ((t & 7) == 0) {
#pragma unroll
                for (int mt = 0; mt < 2; mt++)
#pragma unroll
                    for (int nt = 0; nt < 4; nt++)
#pragma unroll
                        for (int q = 0; q < 4; q++) acc[mt][nt][q] = 0.f;
            }

            {
                const int ks = t & 7;
                const uint32_t aH  = sb + ks * 8192;
                const uint32_t aL  = sb + L2_XL + ks * 8192;
                const uint32_t st  = sb + L2_B0 + (t & 1) * L2_BSTAGE;
                const uint32_t aBh = st, aBl = st + 16384;
#pragma unroll
                for (int kq = 0; kq < 4; kq++) {
                    const int ksg = kq * 2;
                    uint32_t ah[8], al[8], bh[8], bl[8];
#pragma unroll
                    for (int mt = 0; mt < 2; mt++) {
                        const uint32_t offA = (arow + mt * 16) * 128 + (((ksg + ak) ^ arw) << 4);
                        ldsm4(ah + 4 * mt, aH + offA);
                        ldsm4(al + 4 * mt, aL + offA);
                    }
#pragma unroll
                    for (int p = 0; p < 2; p++) {
                        const uint32_t offB = (nrow + p * 16) * 128 + (((ksg + bk) ^ nrw) << 4);
                        ldsm4(bh + 4 * p, aBh + offB);
                        ldsm4(bl + 4 * p, aBl + offB);
                    }
#pragma unroll
                    for (int mt = 0; mt < 2; mt++)
#pragma unroll
                        for (int nt = 0; nt < 4; nt++) {
                            mma16816(acc[mt][nt], ah + 4 * mt, bh + 2 * nt);
                            mma16816(acc[mt][nt], ah + 4 * mt, bl + 2 * nt);
                            mma16816(acc[mt][nt], al + 4 * mt, bh + 2 * nt);
                        }
                }
            }

            if ((t & 7) == 7) {
                const int c   = t >> 3;
                const int cb0 = code0 + (c << 7) + wn * 32 + ((lane & 3) << 1);
#pragma unroll
                for (int mt = 0; mt < 2; mt++)
#pragma unroll
                    for (int nt = 0; nt < 4; nt++) {
                        const int cc = cb0 + nt * 8;
                        const float2 nn = __ldg((const float2*)(g_cn + cc));
                        const int k0 = mt * 2, k1 = mt * 2 + 1;
                        float m;
                        m = fmaf(-2.f, acc[mt][nt][0], nn.x); BUPD(m, cc,     bb[k0], bb2[k0], bi[k0]);
                        m = fmaf(-2.f, acc[mt][nt][1], nn.y); BUPD(m, cc + 1, bb[k0], bb2[k0], bi[k0]);
                        m = fmaf(-2.f, acc[mt][nt][2], nn.x); BUPD(m, cc,     bb[k1], bb2[k1], bi[k1]);
                        m = fmaf(-2.f, acc[mt][nt][3], nn.y); BUPD(m, cc + 1, bb[k1], bb2[k1], bi[k1]);
                    }
            }
            __syncthreads();
        }

        float* rv  = (float*)(smem);
        float* rv2 = rv + 1024;
        int*   ri  = (int*)(rv2 + 1024);
        const int slot = wn * 4 + (lane & 3);
#pragma unroll
        for (int k = 0; k < 4; k++) {
            const int lr = wm * 32 + (k >> 1) * 16 + (lane >> 2) + (k & 1) * 8;
            rv [lr * 16 + slot] = bb[k];
            rv2[lr * 16 + slot] = bb2[k];
            ri [lr * 16 + slot] = bi[k];
        }
        __syncthreads();
        if (tid < 64) {
            float b1 = rv[tid * 16], b2 = rv2[tid * 16];
            int   i1 = ri[tid * 16];
#pragma unroll
            for (int s = 1; s < 16; s++) {
                const float v = rv[tid * 16 + s], v2 = rv2[tid * 16 + s];
                const int   ii = ri[tid * 16 + s];
                BMERGE(v, v2, ii, b1, b2, i1);
            }
            const int slotg = slot0 + tid;
            if (slotg < active) {
                const int o = seg * L2CAP + slotg;
                g_l2v1[o] = b1; g_l2v2[o] = b2; g_l2i[o] = i1;
            }
        }
        __syncthreads();
    }
}

// ---------------- kernel 5: merge level-2 segments ----------------
__global__ void merge2_kernel()
{
    const int active = min(g_counters[0], L2CAP);
    const int slot = blockIdx.x * blockDim.x + threadIdx.x;
    if (slot >= active) return;
    float b1 = 3.0e38f, b2 = 3.0e38f;
    int   i1 = 0;
#pragma unroll
    for (int s = 0; s < 4; s++) {
        const float v  = g_l2v1[s * L2CAP + slot];
        const float v2 = g_l2v2[s * L2CAP + slot];
        const int   ii = g_l2i[s * L2CAP + slot];
        BMERGE(v, v2, ii, b1, b2, i1);
    }
    const int row = g_flaglist[slot];
    g_ids[row] = i1;
    if (b2 - b1 < TAU2) {
        int p = atomicAdd(&g_counters[1], 1);
        g_flaglist2[p] = row;
        g_fix[row] = 0xFFFFFFFFFFFFFFFFull;
    }
}

// ---------------- kernel 6: exact fp32 fixup (gridDim.y = 2) ----------------
__global__ void __launch_bounds__(256, 1)
fixup_kernel(const float* __restrict__ x, const float* __restrict__ cb)
{
    const int cnt = g_counters[1];
    if (cnt == 0) return;
    extern __shared__ float cs[];
    const int b   = blockIdx.x;
    const int tid = threadIdx.x;
    const int lane = tid & 31, warp = tid >> 5;
    {
        const float4* src = (const float4*)(cb + (size_t)b * 64 * DD);
        float4* dst = (float4*)cs;
        for (int i = tid; i < 64 * 128; i += 256) dst[i] = src[i];
    }
    __syncthreads();
    const int code_l = tid >> 2;
    const int part   = tid & 3;
    __shared__ unsigned long long wmin[8];
    for (int r = blockIdx.y; r < cnt; r += gridDim.y) {
        const int row = g_flaglist2[r];
        const float4* xr = (const float4*)(x + (size_t)row * DD) + part * 32;
        const float4* cr = (const float4*)(cs + code_l * DD) + part * 32;
        float s = 0.f;
#pragma unroll 8
        for (int i = 0; i < 32; i++) {
            float4 a = xr[i], c = cr[i];
            float d0 = a.x - c.x, d1 = a.y - c.y, d2 = a.z - c.z, d3 = a.w - c.w;
            s += d0 * d0 + d1 * d1 + d2 * d2 + d3 * d3;
        }
        s += __shfl_xor_sync(0xffffffffu, s, 1);
        s += __shfl_xor_sync(0xffffffffu, s, 2);
        unsigned long long pk =
            (((unsigned long long)__float_as_uint(s)) << 32) | (unsigned)(b * 64 + code_l);
#pragma unroll
        for (int o = 4; o < 32; o <<= 1) {
            unsigned lo = (unsigned)pk, hi = (unsigned)(pk >> 32);
            unsigned olo = __shfl_xor_sync(0xffffffffu, lo, o);
            unsigned ohi = __shfl_xor_sync(0xffffffffu, hi, o);
            unsigned long long opk = (((unsigned long long)ohi) << 32) | olo;
            if (opk < pk) pk = opk;
        }
        if (lane == 0) wmin[warp] = pk;
        __syncthreads();
        if (tid == 0) {
            unsigned long long m = wmin[0];
#pragma unroll
            for (int w = 1; w < 8; w++) if (wmin[w] < m) m = wmin[w];
            atomicMin(&g_fix[row], m);
        }
        __syncthreads();
    }
}

// ---------------- kernel 6b: commit fixup ids ----------------
__global__ void commit_kernel()
{
    const int cnt = g_counters[1];
    const int s = blockIdx.x * blockDim.x + threadIdx.x;
    if (s >= cnt) return;
    const int row = g_flaglist2[s];
    g_ids[row] = (int)(unsigned)(g_fix[row] & 0xffffffffu);
}

// ---------------- kernel 7: gather + ids + loss (2 rows per CTA) ----------------
__global__ void gather_loss_kernel(const float* __restrict__ x,
                                   const float* __restrict__ cb,
                                   float* __restrict__ out, int N)
{
    const int sub = threadIdx.x >> 7;
    const int t   = threadIdx.x & 127;
    const int row = blockIdx.x * 2 + sub;
    const int id  = g_ids[row];
    float4 xv = ((const float4*)(x  + (size_t)row * DD))[t];
    float4 cv = ((const float4*)(cb + (size_t)id  * DD))[t];
    ((float4*)(out + (size_t)row * DD))[t] = cv;
    float dx = xv.x - cv.x, dy = xv.y - cv.y, dz = xv.z - cv.z, dw = xv.w - cv.w;
    float s = dx * dx + dy * dy + dz * dz + dw * dw;
#pragma unroll
    for (int o = 16; o; o >>= 1) s += __shfl_xor_sync(0xffffffffu, s, o);
    __shared__ float ws[8];
    if ((t & 31) == 0) ws[sub * 4 + (t >> 5)] = s;
    __syncthreads();
    if (t == 0) {
        const float tot = ws[sub * 4] + ws[sub * 4 + 1] + ws[sub * 4 + 2] + ws[sub * 4 + 3];
        out[(size_t)N * DD + N + row] = 1.25f * tot;
    }
    if (t == 32) out[(size_t)N * DD + row] = (float)id;
}

// ---------------- host ----------------
extern "C" void kernel_launch(void* const* d_in, const int* in_sizes, int n_in,
                              void* d_out, int out_size)
{
    const float* x  = (const float*)d_in[0];
    const float* cb = (const float*)d_in[1];
    float* out = (float*)d_out;
    const int N = in_sizes[0] / DD;
    const int K = in_sizes[1] / DD;

    void *p_xh, *p_ch, *p_cl, *p_cnt;
    cudaGetSymbolAddress(&p_xh, g_xh);
    cudaGetSymbolAddress(&p_ch, g_ch);
    cudaGetSymbolAddress(&p_cl, g_cl);
    cudaGetSymbolAddress(&p_cnt, g_counters);

    static bool attr_done = false;
    if (!attr_done) {
        cudaFuncSetAttribute(vq_main, cudaFuncAttributeMaxDynamicSharedMemorySize, SMEM_L1);
        cudaFuncSetAttribute(vq_l2,   cudaFuncAttributeMaxDynamicSharedMemorySize, SMEM_L2);
        cudaFuncSetAttribute(fixup_kernel, cudaFuncAttributeMaxDynamicSharedMemorySize, 64 * DD * 4);
        attr_done = true;
    }

    cudaMemsetAsync(p_cnt, 0, 2 * sizeof(int));

    const int n4x = N * DD / 4;
    split_x_kernel<<<(n4x + 255) / 256, 256>>>(x, (__half*)p_xh, n4x);
    split_c_kernel<<<K / 8, 256>>>(cb, (__half*)p_ch, (__half*)p_cl);
    vq_main<<<dim3(N / 128, 4), 256, SMEM_L1>>>();
    merge1_kernel<<<N / 256, 256>>>();
    vq_l2<<<dim3(64, 4), 256, SMEM_L2>>>(x);
    merge2_kernel<<<L2CAP / 256, 256>>>();
    fixup_kernel<<<dim3(K / 64, 2), 256, 64 * DD * 4>>>(x, cb);
    commit_kernel<<<L2CAP / 256, 256>>>();
    gather_loss_kernel<<<N / 2, 256>>>(x, cb, out, N);
}

// round 16
// speedup vs baseline: 1.0488x; 1.0488x over previous
#include <cuda_runtime.h>
#include <cuda_fp16.h>
#include <cstdint>

#define DD    512
#define NROWS 32768
#define KCODE 8192
#define TAU1  0.02f
#define TAU2  1.0e-3f
#define L2CAP 32768

// ---------------- device scratch ----------------
__device__ __align__(1024) __half g_xh[NROWS * DD];
__device__ __align__(1024) __half g_xl[NROWS * DD];
__device__ __align__(1024) __half g_ch[KCODE * DD];
__device__ __align__(1024) __half g_cl[KCODE * DD];
__device__ float              g_cn[KCODE];
__device__ int                g_ids[NROWS];
__device__ float              g_c1v[4 * NROWS], g_c2v[4 * NROWS];
__device__ int                g_c1i[4 * NROWS];
__device__ float              g_l2v1[8 * L2CAP], g_l2v2[8 * L2CAP];
__device__ int                g_l2i[8 * L2CAP];
__device__ int                g_counters[2];
__device__ int                g_flaglist[NROWS], g_flaglist2[NROWS];
__device__ unsigned long long g_fix[NROWS];

// ---------------- helpers ----------------
__device__ __forceinline__ uint32_t smem_u32(const void* p) {
    uint32_t a;
    asm("{ .reg .u64 t; cvta.to.shared.u64 t, %1; cvt.u32.u64 %0, t; }" : "=r"(a) : "l"(p));
    return a;
}
__device__ __forceinline__ void ldsm4(uint32_t* r, uint32_t addr) {
    asm volatile("ldmatrix.sync.aligned.m8n8.x4.shared.b16 {%0,%1,%2,%3}, [%4];"
                 : "=r"(r[0]), "=r"(r[1]), "=r"(r[2]), "=r"(r[3]) : "r"(addr));
}
__device__ __forceinline__ void mma16816(float* c, const uint32_t* a, const uint32_t* b) {
    asm volatile("mma.sync.aligned.m16n8k16.row.col.f32.f16.f16.f32 "
                 "{%0,%1,%2,%3}, {%4,%5,%6,%7}, {%8,%9}, {%0,%1,%2,%3};"
                 : "+f"(c[0]), "+f"(c[1]), "+f"(c[2]), "+f"(c[3])
                 : "r"(a[0]), "r"(a[1]), "r"(a[2]), "r"(a[3]), "r"(b[0]), "r"(b[1]));
}
__device__ __forceinline__ void cp16(uint32_t dst, const void* src) {
    asm volatile("cp.async.cg.shared.global [%0], [%1], 16;" :: "r"(dst), "l"(src));
}
__device__ __forceinline__ void cp_commit() { asm volatile("cp.async.commit_group;" ::: "memory"); }
__device__ __forceinline__ void cp_wait1()  { asm volatile("cp.async.wait_group 1;" ::: "memory"); }
__device__ __forceinline__ void cp_wait2()  { asm volatile("cp.async.wait_group 2;" ::: "memory"); }
__device__ __forceinline__ void cp_wait0()  { asm volatile("cp.async.wait_group 0;" ::: "memory"); }
__device__ __forceinline__ void bar_grp64(int id) {
    asm volatile("bar.sync %0, 64;" :: "r"(id) : "memory");
}

#define BUPD(m, idx, B1, B2, I1) \
    if ((m) < (B2)) { if ((m) < (B1)) { (B2) = (B1); (B1) = (m); (I1) = (idx); } else (B2) = (m); }

#define BMERGE(v, v2, ii, b1, b2, i1) \
    if ((v) < (b1))       { (b2) = fminf((b1), (v2)); (b1) = (v); (i1) = (ii); } \
    else if ((v) == (b1)) { if ((ii) < (i1)) (i1) = (ii); (b2) = fminf((b2), fminf((v), (v2))); } \
    else                  { (b2) = fminf((b2), (v)); }

#define S_B0      131072
#define BSTAGE    32768
#define SMEM_L1   229376
#define L2_XL     65536
#define L2_B0     131072
#define L2_BSTAGE 32768
#define SMEM_L2   196608

// ---------------- kernel 0a: x -> fp16 hi/lo ----------------
__global__ void split_x_kernel(const float* __restrict__ src,
                               __half* __restrict__ hi, __half* __restrict__ lo, int n4)
{
    int i = blockIdx.x * blockDim.x + threadIdx.x;
    if (i >= n4) return;
    float4 v = ((const float4*)src)[i];
    __half h0 = __float2half_rn(v.x), h1 = __float2half_rn(v.y);
    __half h2 = __float2half_rn(v.z), h3 = __float2half_rn(v.w);
    ((__half2*)hi)[i * 2 + 0] = __half2(h0, h1);
    ((__half2*)hi)[i * 2 + 1] = __half2(h2, h3);
    ((__half2*)lo)[i * 2 + 0] = __half2(__float2half_rn(v.x - __half2float(h0)),
                                        __float2half_rn(v.y - __half2float(h1)));
    ((__half2*)lo)[i * 2 + 1] = __half2(__float2half_rn(v.z - __half2float(h2)),
                                        __float2half_rn(v.w - __half2float(h3)));
}

// ---------------- kernel 0b: codebook -> fp16 hi/lo + norms (fused) ----------------
__global__ void split_c_kernel(const float* __restrict__ cb,
                               __half* __restrict__ hi, __half* __restrict__ lo)
{
    const int w = (blockIdx.x * blockDim.x + threadIdx.x) >> 5;
    const int lane = threadIdx.x & 31;
    const float4* p = (const float4*)(cb + (size_t)w * DD);
    __half2* ph = (__half2*)(hi + (size_t)w * DD);
    __half2* pl = (__half2*)(lo + (size_t)w * DD);
    float s = 0.f;
#pragma unroll
    for (int i = 0; i < 4; i++) {
        const int e4 = lane + 32 * i;
        float4 v = p[e4];
        s += v.x * v.x + v.y * v.y + v.z * v.z + v.w * v.w;
        __half h0 = __float2half_rn(v.x), h1 = __float2half_rn(v.y);
        __half h2 = __float2half_rn(v.z), h3 = __float2half_rn(v.w);
        ph[e4 * 2 + 0] = __half2(h0, h1);
        ph[e4 * 2 + 1] = __half2(h2, h3);
        pl[e4 * 2 + 0] = __half2(__float2half_rn(v.x - __half2float(h0)),
                                 __float2half_rn(v.y - __half2float(h1)));
        pl[e4 * 2 + 1] = __half2(__float2half_rn(v.z - __half2float(h2)),
                                 __float2half_rn(v.w - __half2float(h3)));
    }
#pragma unroll
    for (int o = 16; o; o >>= 1) s += __shfl_xor_sync(0xffffffffu, s, o);
    if (lane == 0) g_cn[w] = s;
}

// ---------------- kernel 2: level-1 2-pass HMMA, FOUR independent warp-pairs ----------------
__global__ void __launch_bounds__(256, 1)
vq_main()
{
    extern __shared__ char smem[];
    const uint32_t sb = smem_u32(smem);

    const int tid   = threadIdx.x;
    const int lane  = tid & 31;
    const int warp  = tid >> 5;
    const int g     = warp >> 1;
    const int whalf = warp & 1;
    const int gtid  = tid & 63;
    const int g32   = g * 32;
    const int row0  = blockIdx.x * 128;
    const int split = blockIdx.y;
    const int code_base = split * 2048;

    const int arow = whalf * 64 + (lane & 15);
    const int ak   = lane >> 4;
    const int arw  = arow & 7;
    const int nrow = g32 + ((lane >> 4) << 3) + (lane & 7);
    const int bk   = (lane >> 3) & 1;
    const int nrw  = nrow & 7;

    float acc[4][4][4];
    float bb[8], bb2[8];
    int   bi[8];
    float2 nrm[4];
#pragma unroll
    for (int k = 0; k < 8; k++) { bb[k] = 3.0e38f; bb2[k] = 3.0e38f; bi[k] = 0; }

    auto issueB = [&](int t, int stg) {
        const int c = t >> 3, ks = t & 7;
        const uint32_t st = sb + S_B0 + stg * BSTAGE;
        const size_t base = (size_t)(code_base + c * 128) * DD + (size_t)ks * 64;
#pragma unroll
        for (int i = 0; i < 4; i++) {
            const int idx = gtid + i * 64;
            const int r = g32 + (idx >> 3), sg = idx & 7;
            const uint32_t off = r * 128 + ((sg ^ (r & 7)) << 4);
            const size_t bo = base + (size_t)r * DD + sg * 8;
            cp16(st + off,         g_ch + bo);
            cp16(st + 16384 + off, g_cl + bo);
        }
        cp_commit();
    };

    {
#pragma unroll
        for (int i = 0; i < 32; i++) {
            const int idx = tid + i * 256;
            const int r = idx >> 6, gg = idx & 63;
            const int s = gg >> 3, sg = gg & 7;
            const uint32_t dst = sb + s * 16384 + r * 128 + ((sg ^ (r & 7)) << 4);
            cp16(dst, g_xh + (size_t)(row0 + r) * DD + gg * 8);
        }
        cp_commit();
        issueB(0, 0);
        issueB(1, 1);
        cp_wait2();
        __syncthreads();
    }

    auto loadf = [&](uint32_t* ahb, uint32_t* bhb, uint32_t* blb, int kq,
                     uint32_t aA, uint32_t aBh, uint32_t aBl) {
        const int ksg = kq * 2;
#pragma unroll
        for (int mt = 0; mt < 4; mt++) {
            const uint32_t offA = (arow + mt * 16) * 128 + (((ksg + ak) ^ arw) << 4);
            ldsm4(ahb + 4 * mt, aA + offA);
        }
#pragma unroll
        for (int p = 0; p < 2; p++) {
            const uint32_t offB = (nrow + p * 16) * 128 + (((ksg + bk) ^ nrw) << 4);
            ldsm4(bhb + 4 * p, aBh + offB);
            ldsm4(blb + 4 * p, aBl + offB);
        }
    };

    const int barid = 1 + g;
    int scur = 0, snxt2 = 2;
#pragma unroll 1
    for (int t = 0; t < 128; t++) {
        cp_wait1();
        bar_grp64(barid);
        if (t + 2 < 128) issueB(t + 2, snxt2);

        if ((t & 7) == 0) {
            const int c = t >> 3;
            const int ccl0 = code_base + (c << 7) + g32 + ((lane & 3) << 1);
#pragma unroll
            for (int nt = 0; nt < 4; nt++)
                nrm[nt] = __ldg((const float2*)(g_cn + ccl0 + nt * 8));
#pragma unroll
            for (int mt = 0; mt < 4; mt++)
#pragma unroll
                for (int nt = 0; nt < 4; nt++)
#pragma unroll
                    for (int q = 0; q < 4; q++) acc[mt][nt][q] = 0.f;
        }

        {
            const int ks = t & 7;
            const uint32_t aA  = sb + ks * 16384;
            const uint32_t st  = sb + S_B0 + scur * BSTAGE;
            const uint32_t aBh = st, aBl = st + 16384;

            uint32_t ah[2][16], bh[2][8], bl[2][8];
            loadf(ah[0], bh[0], bl[0], 0, aA, aBh, aBl);
#pragma unroll
            for (int kq = 0; kq < 4; kq++) {
                const int cur = kq & 1;
                if (kq < 3) loadf(ah[cur ^ 1], bh[cur ^ 1], bl[cur ^ 1], kq + 1, aA, aBh, aBl);
#pragma unroll
                for (int mt = 0; mt < 4; mt++)
#pragma unroll
                    for (int nt = 0; nt < 4; nt++) {
                        mma16816(acc[mt][nt], ah[cur] + 4 * mt, bh[cur] + 2 * nt);
                        mma16816(acc[mt][nt], ah[cur] + 4 * mt, bl[cur] + 2 * nt);
                    }
            }
        }

        if ((t & 7) == 7) {
            const int c   = t >> 3;
            const int cb0 = code_base + (c << 7) + g32 + ((lane & 3) << 1);
#pragma unroll
            for (int mt = 0; mt < 4; mt++)
#pragma unroll
                for (int nt = 0; nt < 4; nt++) {
                    const int cc = cb0 + nt * 8;
                    const float n0 = nrm[nt].x, n1 = nrm[nt].y;
                    const int k0 = mt * 2, k1 = mt * 2 + 1;
                    float m;
                    m = fmaf(-2.f, acc[mt][nt][0], n0); BUPD(m, cc,     bb[k0], bb2[k0], bi[k0]);
                    m = fmaf(-2.f, acc[mt][nt][1], n1); BUPD(m, cc + 1, bb[k0], bb2[k0], bi[k0]);
                    m = fmaf(-2.f, acc[mt][nt][2], n0); BUPD(m, cc,     bb[k1], bb2[k1], bi[k1]);
                    m = fmaf(-2.f, acc[mt][nt][3], n1); BUPD(m, cc + 1, bb[k1], bb2[k1], bi[k1]);
                }
        }

        scur  = (scur  == 2) ? 0 : scur + 1;
        snxt2 = (snxt2 == 2) ? 0 : snxt2 + 1;
    }

    __syncthreads();
    float* rv  = (float*)(smem);
    float* rv2 = rv + 2048;
    int*   ri  = (int*)(rv2 + 2048);
    const int slot = g * 4 + (lane & 3);
#pragma unroll
    for (int mt = 0; mt < 4; mt++)
#pragma unroll
        for (int h = 0; h < 2; h++) {
            const int k  = mt * 2 + h;
            const int lr = whalf * 64 + mt * 16 + (lane >> 2) + h * 8;
            rv [lr * 16 + slot] = bb[k];
            rv2[lr * 16 + slot] = bb2[k];
            ri [lr * 16 + slot] = bi[k];
        }
    __syncthreads();
    if (tid < 128) {
        float b1 = rv[tid * 16], b2 = rv2[tid * 16];
        int   i1 = ri[tid * 16];
#pragma unroll
        for (int s = 1; s < 16; s++) {
            const float v = rv[tid * 16 + s], v2 = rv2[tid * 16 + s];
            const int   ii = ri[tid * 16 + s];
            BMERGE(v, v2, ii, b1, b2, i1);
        }
        const int o = split * NROWS + row0 + tid;
        g_c1v[o] = b1; g_c2v[o] = b2; g_c1i[o] = i1;
    }
}

// ---------------- kernel 3: merge level-1 splits ----------------
__global__ void merge1_kernel()
{
    const int row = blockIdx.x * blockDim.x + threadIdx.x;
    if (row >= NROWS) return;
    float b1 = 3.0e38f, b2 = 3.0e38f;
    int   i1 = 0;
#pragma unroll
    for (int s = 0; s < 4; s++) {
        const float v  = g_c1v[s * NROWS + row];
        const float v2 = g_c2v[s * NROWS + row];
        const int   ii = g_c1i[s * NROWS + row];
        BMERGE(v, v2, ii, b1, b2, i1);
    }
    g_ids[row] = i1;
    if (b2 - b1 < TAU1) {
        int p = atomicAdd(&g_counters[0], 1);
        if (p < L2CAP) g_flaglist[p] = row;
    }
}

// ---------------- kernel 4: level-2 3-pass HMMA rescore (persistent, grid 32x8) ----------------
__global__ void __launch_bounds__(256, 1)
vq_l2()
{
    const int active = min(g_counters[0], L2CAP);
    extern __shared__ char smem[];
    const uint32_t sb = smem_u32(smem);

    const int tid  = threadIdx.x;
    const int lane = tid & 31;
    const int warp = tid >> 5;
    const int wm   = warp >> 2;
    const int wn   = warp & 3;
    const int seg  = blockIdx.y;
    const int code0 = seg * 1024;

    const int arow = wm * 32 + (lane & 15);
    const int ak   = lane >> 4;
    const int arw  = arow & 7;
    const int nrow = wn * 32 + ((lane >> 4) << 3) + (lane & 7);
    const int bk   = (lane >> 3) & 1;
    const int nrw  = nrow & 7;

    auto issueB = [&](int t) {
        const int c = t >> 3, ks = t & 7;
        const uint32_t st = sb + L2_B0 + (t & 1) * L2_BSTAGE;
        const size_t base = (size_t)(code0 + c * 128) * DD + (size_t)ks * 64;
#pragma unroll
        for (int i = 0; i < 4; i++) {
            const int idx = tid + i * 256;
            const int r = idx >> 3, sg = idx & 7;
            const uint32_t off = r * 128 + ((sg ^ (r & 7)) << 4);
            const size_t bo = base + (size_t)r * DD + sg * 8;
            cp16(st + off,         g_ch + bo);
            cp16(st + 16384 + off, g_cl + bo);
        }
        cp_commit();
    };

#pragma unroll 1
    for (int slot0 = blockIdx.x * 64; slot0 < active; slot0 += gridDim.x * 64) {
        float acc[2][4][4];
        float bb[4], bb2[4];
        int   bi[4];
#pragma unroll
        for (int k = 0; k < 4; k++) { bb[k] = 3.0e38f; bb2[k] = 3.0e38f; bi[k] = 0; }

        {
#pragma unroll
            for (int i = 0; i < 16; i++) {
                const int idx = tid + i * 256;
                const int r = idx >> 6, gg = idx & 63;
                const int s = gg >> 3, sg = gg & 7;
                const int sl = slot0 + r;
                const int grow = __ldg(&g_flaglist[sl < active ? sl : slot0]);
                const uint32_t dst = s * 8192 + r * 128 + ((sg ^ (r & 7)) << 4);
                cp16(sb + dst,           g_xh + (size_t)grow * DD + gg * 8);
                cp16(sb + L2_XL + dst,   g_xl + (size_t)grow * DD + gg * 8);
            }
            const uint32_t st = sb + L2_B0;
            const size_t base = (size_t)code0 * DD;
#pragma unroll
            for (int i = 0; i < 4; i++) {
                const int idx = tid + i * 256;
                const int r = idx >> 3, sg = idx & 7;
                const uint32_t off = r * 128 + ((sg ^ (r & 7)) << 4);
                const size_t bo = base + (size_t)r * DD + sg * 8;
                cp16(st + off,         g_ch + bo);
                cp16(st + 16384 + off, g_cl + bo);
            }
            cp_commit();
        }

#pragma unroll 1
        for (int t = 0; t < 64; t++) {
            if (t + 1 < 64) { issueB(t + 1); cp_wait1(); }
            else            { cp_wait0(); }
            __syncthreads();

            if ((t & 7) == 0) {
#pragma unroll
                for (int mt = 0; mt < 2; mt++)
#pragma unroll
                    for (int nt = 0; nt < 4; nt++)
#pragma unroll
                        for (int q = 0; q < 4; q++) acc[mt][nt][q] = 0.f;
            }

            {
                const int ks = t & 7;
                const uint32_t aH  = sb + ks * 8192;
                const uint32_t aL  = sb + L2_XL + ks * 8192;
                const uint32_t st  = sb + L2_B0 + (t & 1) * L2_BSTAGE;
                const uint32_t aBh = st, aBl = st + 16384;
#pragma unroll
                for (int kq = 0; kq < 4; kq++) {
                    const int ksg = kq * 2;
                    uint32_t ah[8], al[8], bh[8], bl[8];
#pragma unroll
                    for (int mt = 0; mt < 2; mt++) {
                        const uint32_t offA = (arow + mt * 16) * 128 + (((ksg + ak) ^ arw) << 4);
                        ldsm4(ah + 4 * mt, aH + offA);
                        ldsm4(al + 4 * mt, aL + offA);
                    }
#pragma unroll
                    for (int p = 0; p < 2; p++) {
                        const uint32_t offB = (nrow + p * 16) * 128 + (((ksg + bk) ^ nrw) << 4);
                        ldsm4(bh + 4 * p, aBh + offB);
                        ldsm4(bl + 4 * p, aBl + offB);
                    }
#pragma unroll
                    for (int mt = 0; mt < 2; mt++)
#pragma unroll
                        for (int nt = 0; nt < 4; nt++) {
                            mma16816(acc[mt][nt], ah + 4 * mt, bh + 2 * nt);
                            mma16816(acc[mt][nt], ah + 4 * mt, bl + 2 * nt);
                            mma16816(acc[mt][nt], al + 4 * mt, bh + 2 * nt);
                        }
                }
            }

            if ((t & 7) == 7) {
                const int c   = t >> 3;
                const int cb0 = code0 + (c << 7) + wn * 32 + ((lane & 3) << 1);
#pragma unroll
                for (int mt = 0; mt < 2; mt++)
#pragma unroll
                    for (int nt = 0; nt < 4; nt++) {
                        const int cc = cb0 + nt * 8;
                        const float2 nn = __ldg((const float2*)(g_cn + cc));
                        const int k0 = mt * 2, k1 = mt * 2 + 1;
                        float m;
                        m = fmaf(-2.f, acc[mt][nt][0], nn.x); BUPD(m, cc,     bb[k0], bb2[k0], bi[k0]);
                        m = fmaf(-2.f, acc[mt][nt][1], nn.y); BUPD(m, cc + 1, bb[k0], bb2[k0], bi[k0]);
                        m = fmaf(-2.f, acc[mt][nt][2], nn.x); BUPD(m, cc,     bb[k1], bb2[k1], bi[k1]);
                        m = fmaf(-2.f, acc[mt][nt][3], nn.y); BUPD(m, cc + 1, bb[k1], bb2[k1], bi[k1]);
                    }
            }
            __syncthreads();
        }

        float* rv  = (float*)(smem);
        float* rv2 = rv + 1024;
        int*   ri  = (int*)(rv2 + 1024);
        const int slot = wn * 4 + (lane & 3);
#pragma unroll
        for (int k = 0; k < 4; k++) {
            const int lr = wm * 32 + (k >> 1) * 16 + (lane >> 2) + (k & 1) * 8;
            rv [lr * 16 + slot] = bb[k];
            rv2[lr * 16 + slot] = bb2[k];
            ri [lr * 16 + slot] = bi[k];
        }
        __syncthreads();
        if (tid < 64) {
            float b1 = rv[tid * 16], b2 = rv2[tid * 16];
            int   i1 = ri[tid * 16];
#pragma unroll
            for (int s = 1; s < 16; s++) {
                const float v = rv[tid * 16 + s], v2 = rv2[tid * 16 + s];
                const int   ii = ri[tid * 16 + s];
                BMERGE(v, v2, ii, b1, b2, i1);
            }
            const int slotg = slot0 + tid;
            if (slotg < active) {
                const int o = seg * L2CAP + slotg;
                g_l2v1[o] = b1; g_l2v2[o] = b2; g_l2i[o] = i1;
            }
        }
        __syncthreads();
    }
}

// ---------------- kernel 5: merge level-2 segments ----------------
__global__ void merge2_kernel()
{
    const int active = min(g_counters[0], L2CAP);
    const int slot = blockIdx.x * blockDim.x + threadIdx.x;
    if (slot >= active) return;
    float b1 = 3.0e38f, b2 = 3.0e38f;
    int   i1 = 0;
#pragma unroll
    for (int s = 0; s < 8; s++) {
        const float v  = g_l2v1[s * L2CAP + slot];
        const float v2 = g_l2v2[s * L2CAP + slot];
        const int   ii = g_l2i[s * L2CAP + slot];
        BMERGE(v, v2, ii, b1, b2, i1);
    }
    const int row = g_flaglist[slot];
    g_ids[row] = i1;
    if (b2 - b1 < TAU2) {
        int p = atomicAdd(&g_counters[1], 1);
        g_flaglist2[p] = row;
        g_fix[row] = 0xFFFFFFFFFFFFFFFFull;
    }
}

// ---------------- kernel 6: exact fp32 fixup (gridDim.y = 2) ----------------
__global__ void __launch_bounds__(256, 1)
fixup_kernel(const float* __restrict__ x, const float* __restrict__ cb)
{
    const int cnt = g_counters[1];
    if (cnt == 0) return;
    extern __shared__ float cs[];
    const int b   = blockIdx.x;
    const int tid = threadIdx.x;
    const int lane = tid & 31, warp = tid >> 5;
    {
        const float4* src = (const float4*)(cb + (size_t)b * 64 * DD);
        float4* dst = (float4*)cs;
        for (int i = tid; i < 64 * 128; i += 256) dst[i] = src[i];
    }
    __syncthreads();
    const int code_l = tid >> 2;
    const int part   = tid & 3;
    __shared__ unsigned long long wmin[8];
    for (int r = blockIdx.y; r < cnt; r += gridDim.y) {
        const int row = g_flaglist2[r];
        const float4* xr = (const float4*)(x + (size_t)row * DD) + part * 32;
        const float4* cr = (const float4*)(cs + code_l * DD) + part * 32;
        float s = 0.f;
#pragma unroll 8
        for (int i = 0; i < 32; i++) {
            float4 a = xr[i], c = cr[i];
            float d0 = a.x - c.x, d1 = a.y - c.y, d2 = a.z - c.z, d3 = a.w - c.w;
            s += d0 * d0 + d1 * d1 + d2 * d2 + d3 * d3;
        }
        s += __shfl_xor_sync(0xffffffffu, s, 1);
        s += __shfl_xor_sync(0xffffffffu, s, 2);
        unsigned long long pk =
            (((unsigned long long)__float_as_uint(s)) << 32) | (unsigned)(b * 64 + code_l);
#pragma unroll
        for (int o = 4; o < 32; o <<= 1) {
            unsigned lo = (unsigned)pk, hi = (unsigned)(pk >> 32);
            unsigned olo = __shfl_xor_sync(0xffffffffu, lo, o);
            unsigned ohi = __shfl_xor_sync(0xffffffffu, hi, o);
            unsigned long long opk = (((unsigned long long)ohi) << 32) | olo;
            if (opk < pk) pk = opk;
        }
        if (lane == 0) wmin[warp] = pk;
        __syncthreads();
        if (tid == 0) {
            unsigned long long m = wmin[0];
#pragma unroll
            for (int w = 1; w < 8; w++) if (wmin[w] < m) m = wmin[w];
            atomicMin(&g_fix[row], m);
        }
        __syncthreads();
    }
}

// ---------------- kernel 6b: commit fixup ids ----------------
__global__ void commit_kernel()
{
    const int cnt = g_counters[1];
    const int s = blockIdx.x * blockDim.x + threadIdx.x;
    if (s >= cnt) return;
    const int row = g_flaglist2[s];
    g_ids[row] = (int)(unsigned)(g_fix[row] & 0xffffffffu);
}

// ---------------- kernel 7: gather + ids + loss ----------------
__global__ void gather_loss_kernel(const float* __restrict__ x,
                                   const float* __restrict__ cb,
                                   float* __restrict__ out, int N)
{
    const int row = blockIdx.x;
    const int t   = threadIdx.x;
    const int id  = g_ids[row];
    float4 xv = ((const float4*)(x  + (size_t)row * DD))[t];
    float4 cv = ((const float4*)(cb + (size_t)id  * DD))[t];
    ((float4*)(out + (size_t)row * DD))[t] = cv;
    float dx = xv.x - cv.x, dy = xv.y - cv.y, dz = xv.z - cv.z, dw = xv.w - cv.w;
    float s = dx * dx + dy * dy + dz * dz + dw * dw;
#pragma unroll
    for (int o = 16; o; o >>= 1) s += __shfl_xor_sync(0xffffffffu, s, o);
    __shared__ float ws[4];
    if ((t & 31) == 0) ws[t >> 5] = s;
    __syncthreads();
    if (t == 0) out[(size_t)N * DD + N + row] = 1.25f * (ws[0] + ws[1] + ws[2] + ws[3]);
    if (t == 32) out[(size_t)N * DD + row] = (float)id;
}

// ---------------- host ----------------
extern "C" void kernel_launch(void* const* d_in, const int* in_sizes, int n_in,
                              void* d_out, int out_size)
{
    const float* x  = (const float*)d_in[0];
    const float* cb = (const float*)d_in[1];
    float* out = (float*)d_out;
    const int N = in_sizes[0] / DD;
    const int K = in_sizes[1] / DD;

    void *p_xh, *p_xl, *p_ch, *p_cl, *p_cnt;
    cudaGetSymbolAddress(&p_xh, g_xh);
    cudaGetSymbolAddress(&p_xl, g_xl);
    cudaGetSymbolAddress(&p_ch, g_ch);
    cudaGetSymbolAddress(&p_cl, g_cl);
    cudaGetSymbolAddress(&p_cnt, g_counters);

    static bool attr_done = false;
    if (!attr_done) {
        cudaFuncSetAttribute(vq_main, cudaFuncAttributeMaxDynamicSharedMemorySize, SMEM_L1);
        cudaFuncSetAttribute(vq_l2,   cudaFuncAttributeMaxDynamicSharedMemorySize, SMEM_L2);
        cudaFuncSetAttribute(fixup_kernel, cudaFuncAttributeMaxDynamicSharedMemorySize, 64 * DD * 4);
        attr_done = true;
    }

    cudaMemsetAsync(p_cnt, 0, 2 * sizeof(int));

    const int n4x = N * DD / 4;
    split_x_kernel<<<(n4x + 255) / 256, 256>>>(x, (__half*)p_xh, (__half*)p_xl, n4x);
    split_c_kernel<<<K / 8, 256>>>(cb, (__half*)p_ch, (__half*)p_cl);
    vq_main<<<dim3(N / 128, 4), 256, SMEM_L1>>>();
    merge1_kernel<<<N / 256, 256>>>();
    vq_l2<<<dim3(32, 8), 256, SMEM_L2>>>();
    merge2_kernel<<<L2CAP / 256, 256>>>();
    fixup_kernel<<<dim3(K / 64, 2), 256, 64 * DD * 4>>>(x, cb);
    commit_kernel<<<L2CAP / 256, 256>>>();
    gather_loss_kernel<<<N, 128>>>(x, cb, out, N);
}